// round 15
// baseline (speedup 1.0000x reference)
#include <cuda_runtime.h>
#include <cuda_fp16.h>
#include <cstdint>

// DistMult decoder: out[e] = sigmoid( sum_d x[l,d] * R[t,d] * x[r,d] )
// E = 4M edges, D = 32. x and R in fp16 tables (row = 64B).
//
// R14 state: 47.6us; L1-busy ~32us = wavefront floor (2 lines/edge,
// irreducible). R15: cut fma-pipe work — after h2->f2 conversion, do the dot
// with packed f32x2 (mul.rn.f32x2 + 3x fma.rn.f32x2 + unpack-add) instead of
// 8 scalar FFMA. IEEE fp32 lanes -> no precision change.

#define DIM 32
#define MAX_NODES 100000
#define MAX_REL 1024

__device__ __align__(16) __half g_xh[MAX_NODES * DIM];   // 6.4 MB
__device__ __align__(16) __half g_rh[MAX_REL * DIM];     // 64 KB

__global__ void __launch_bounds__(256) convert_kernel(
    const float2* __restrict__ xin, int n2x,
    const float2* __restrict__ rin, int n2r)
{
    int i = blockIdx.x * blockDim.x + threadIdx.x;
    if (i < n2x) {
        reinterpret_cast<__half2*>(g_xh)[i] = __float22half2_rn(xin[i]);
    } else if (i < n2x + n2r) {
        int j = i - n2x;
        reinterpret_cast<__half2*>(g_rh)[j] = __float22half2_rn(rin[j]);
    }
}

__device__ __forceinline__ unsigned long long pkf2(float2 v) {
    unsigned long long r;
    asm("mov.b64 %0, {%1, %2};" : "=l"(r) : "f"(v.x), "f"(v.y));
    return r;
}
__device__ __forceinline__ unsigned long long mul2(unsigned long long a, unsigned long long b) {
    unsigned long long r;
    asm("mul.rn.f32x2 %0, %1, %2;" : "=l"(r) : "l"(a), "l"(b));
    return r;
}
__device__ __forceinline__ unsigned long long fma2(unsigned long long a, unsigned long long b, unsigned long long c) {
    unsigned long long r;
    asm("fma.rn.f32x2 %0, %1, %2, %3;" : "=l"(r) : "l"(a), "l"(b), "l"(c));
    return r;
}
__device__ __forceinline__ float hadd2(unsigned long long v) {
    float lo, hi;
    asm("mov.b64 {%0, %1}, %2;" : "=f"(lo), "=f"(hi) : "l"(v));
    return lo + hi;
}

// 8-dim partial dot: p = a*b in fp16 (HMUL2), convert, f32x2 dot with c.
__device__ __forceinline__ float edge_score8(const uint4& A, const uint4& B,
                                             const unsigned long long* c2)
{
    const __half2* ah = reinterpret_cast<const __half2*>(&A);
    const __half2* bh = reinterpret_cast<const __half2*>(&B);
    __half2 p0 = __hmul2(ah[0], bh[0]);
    __half2 p1 = __hmul2(ah[1], bh[1]);
    __half2 p2 = __hmul2(ah[2], bh[2]);
    __half2 p3 = __hmul2(ah[3], bh[3]);
    unsigned long long f0 = pkf2(__half22float2(p0));
    unsigned long long f1 = pkf2(__half22float2(p1));
    unsigned long long f2 = pkf2(__half22float2(p2));
    unsigned long long f3 = pkf2(__half22float2(p3));
    unsigned long long acc = mul2(f0, c2[0]);
    acc = fma2(f1, c2[1], acc);
    acc = fma2(f2, c2[2], acc);
    acc = fma2(f3, c2[3], acc);
    return hadd2(acc);
}

// convert fp16 relation row chunk -> 4 packed f32x2
__device__ __forceinline__ void cvt_c2(const uint4& C, unsigned long long* c2)
{
    const __half2* chh = reinterpret_cast<const __half2*>(&C);
    c2[0] = pkf2(__half22float2(chh[0]));
    c2[1] = pkf2(__half22float2(chh[1]));
    c2[2] = pkf2(__half22float2(chh[2]));
    c2[3] = pkf2(__half22float2(chh[3]));
}

__global__ void __launch_bounds__(128, 9) distmult_kernel(
    const int* __restrict__ edge_index,  // [2, E] int32
    const int* __restrict__ edge_type,   // [E] int32
    float* __restrict__ out,
    int E)
{
    int tid = blockIdx.x * blockDim.x + threadIdx.x;
    int g = tid >> 2;               // 4-lane group; handles edges 4g..4g+3
    unsigned i = threadIdx.x & 3u;  // 16B chunk within a 64B fp16 row
    int e0 = g * 4;
    if (e0 >= E) return;

    const uint4* __restrict__ xh = reinterpret_cast<const uint4*>(g_xh);  // row = 4 uint4
    const uint4* __restrict__ rh = reinterpret_cast<const uint4*>(g_rh);

    if (e0 + 3 < E) {
        int4 L  = reinterpret_cast<const int4*>(edge_index)[g];
        int4 Rt = reinterpret_cast<const int4*>(edge_index + E)[g];
        int t0 = edge_type[e0];
        int t3 = edge_type[e0 + 3];

        // 8 independent coalesced 16B gathers; warp covers 8 rows/instruction
        uint4 a0 = xh[(unsigned)L.x * 4u + i];
        uint4 a1 = xh[(unsigned)L.y * 4u + i];
        uint4 a2 = xh[(unsigned)L.z * 4u + i];
        uint4 a3 = xh[(unsigned)L.w * 4u + i];
        uint4 b0 = xh[(unsigned)Rt.x * 4u + i];
        uint4 b1 = xh[(unsigned)Rt.y * 4u + i];
        uint4 b2 = xh[(unsigned)Rt.z * 4u + i];
        uint4 b3 = xh[(unsigned)Rt.w * 4u + i];
        // hoisted: shared-relation row load overlaps the gathers above
        uint4 C0 = rh[(unsigned)t0 * 4u + i];

        float s0, s1, s2, s3;
        if (t0 == t3) {
            // sorted types: one shared R row (~99.9% of groups)
            unsigned long long c2[4];
            cvt_c2(C0, c2);
            s0 = edge_score8(a0, b0, c2);
            s1 = edge_score8(a1, b1, c2);
            s2 = edge_score8(a2, b2, c2);
            s3 = edge_score8(a3, b3, c2);
        } else {
            // relation boundary inside the group (rare)
            unsigned long long c2[4];
            uint4 C;
            cvt_c2(C0, c2);                                              s0 = edge_score8(a0, b0, c2);
            C = rh[(unsigned)edge_type[e0 + 1] * 4u + i]; cvt_c2(C, c2); s1 = edge_score8(a1, b1, c2);
            C = rh[(unsigned)edge_type[e0 + 2] * 4u + i]; cvt_c2(C, c2); s2 = edge_score8(a2, b2, c2);
            C = rh[(unsigned)t3 * 4u + i];                cvt_c2(C, c2); s3 = edge_score8(a3, b3, c2);
        }

        // packed 4-lane reduction of 4 values: 3 SHFLs
        bool b2sel = (i & 2u) != 0u;
        float kA = b2sel ? s1 : s0, sA = b2sel ? s0 : s1;
        kA += __shfl_xor_sync(0xFFFFFFFFu, sA, 2);
        float kB = b2sel ? s3 : s2, sB = b2sel ? s2 : s3;
        kB += __shfl_xor_sync(0xFFFFFFFFu, sB, 2);
        bool b1sel = (i & 1u) != 0u;
        float keep = b1sel ? kB : kA, send = b1sel ? kA : kB;
        keep += __shfl_xor_sync(0xFFFFFFFFu, send, 1);
        // lane i holds edge e0 + (((i&1)<<1) | (i>>1)): lanes {0,1,2,3} -> edges {0,2,1,3}

        int j = (int)(((i & 1u) << 1) | (i >> 1));
        out[e0 + j] = 1.0f / (1.0f + __expf(-keep));  // 32 consecutive floats per warp
    } else {
        // scalar tail (unused when E % 4 == 0, kept for safety)
        for (int e = e0; e < E; e++) {
            int l = edge_index[e];
            int r = edge_index[E + e];
            int t = edge_type[e];
            uint4 a = xh[(unsigned)l * 4u + i];
            uint4 b = xh[(unsigned)r * 4u + i];
            uint4 C = rh[(unsigned)t * 4u + i];
            unsigned long long c2[4];
            cvt_c2(C, c2);
            float s = edge_score8(a, b, c2);
            s += __shfl_xor_sync(0xFFFFFFFFu, s, 1);
            s += __shfl_xor_sync(0xFFFFFFFFu, s, 2);
            if (i == 0u) out[e] = 1.0f / (1.0f + __expf(-s));
        }
    }
}

extern "C" void kernel_launch(void* const* d_in, const int* in_sizes, int n_in,
                              void* d_out, int out_size)
{
    const float* x  = (const float*)d_in[0];   // [N_NODES, 32] fp32
    const float* R  = (const float*)d_in[1];   // [N_REL, 32] fp32
    const int*   ei = (const int*)d_in[2];     // [2, E] int32
    const int*   et = (const int*)d_in[3];     // [E] int32
    float* out = (float*)d_out;

    int E = in_sizes[3];
    int n2x = in_sizes[0] / 2;   // float pairs in x
    int n2r = in_sizes[1] / 2;   // float pairs in R

    // Kernel 1: fp32 -> fp16 tables for x and R
    {
        const int threads = 256;
        int total = n2x + n2r;
        int blocks = (total + threads - 1) / threads;
        convert_kernel<<<blocks, threads>>>(reinterpret_cast<const float2*>(x), n2x,
                                            reinterpret_cast<const float2*>(R), n2r);
    }

    // Kernel 2: gather + score
    {
        const int threads = 128;
        long long groups = ((long long)E + 3) / 4;   // 4 edges per 4-lane group
        long long total = groups * 4;
        int blocks = (int)((total + threads - 1) / threads);
        distmult_kernel<<<blocks, threads>>>(ei, et, out, E);
    }
}

// round 16
// speedup vs baseline: 1.5442x; 1.5442x over previous
#include <cuda_runtime.h>
#include <cuda_fp16.h>
#include <cstdint>

// DistMult decoder: out[e] = sigmoid( sum_d x[l,d] * R[t,d] * x[r,d] )
// E = 4M edges, D = 32. x and R in fp16 tables (row = 64B).
//
// R15 lesson: f32x2 packed math runs on the slow FP64 datapath on sm_103a ->
// big regression; reverted to the R14 scalar-FFMA form.
// Model: R14 moves 512MB through L2 in 46us = ~6300 B/cyc = the measured
// practical LTS cap. R16: only knob left is overlap -> 10 blocks/SM
// (51-reg ceiling, -9% regs; R6's serialization failure was at -17%).

#define DIM 32
#define MAX_NODES 100000
#define MAX_REL 1024

__device__ __align__(16) __half g_xh[MAX_NODES * DIM];   // 6.4 MB
__device__ __align__(16) __half g_rh[MAX_REL * DIM];     // 64 KB

__global__ void __launch_bounds__(256) convert_kernel(
    const float2* __restrict__ xin, int n2x,
    const float2* __restrict__ rin, int n2r)
{
    int i = blockIdx.x * blockDim.x + threadIdx.x;
    if (i < n2x) {
        reinterpret_cast<__half2*>(g_xh)[i] = __float22half2_rn(xin[i]);
    } else if (i < n2x + n2r) {
        int j = i - n2x;
        reinterpret_cast<__half2*>(g_rh)[j] = __float22half2_rn(rin[j]);
    }
}

// 8-dim partial dot: p = a*b in fp16 (HMUL2), then fp32 fma with c.
__device__ __forceinline__ float edge_score8(const uint4& A, const uint4& B, const float* c)
{
    const __half2* ah = reinterpret_cast<const __half2*>(&A);
    const __half2* bh = reinterpret_cast<const __half2*>(&B);
    __half2 p0 = __hmul2(ah[0], bh[0]);
    __half2 p1 = __hmul2(ah[1], bh[1]);
    __half2 p2 = __hmul2(ah[2], bh[2]);
    __half2 p3 = __hmul2(ah[3], bh[3]);
    float2 f0 = __half22float2(p0);
    float2 f1 = __half22float2(p1);
    float2 f2 = __half22float2(p2);
    float2 f3 = __half22float2(p3);
    float s = f0.x * c[0];
    s = fmaf(f0.y, c[1], s);
    s = fmaf(f1.x, c[2], s);
    s = fmaf(f1.y, c[3], s);
    s = fmaf(f2.x, c[4], s);
    s = fmaf(f2.y, c[5], s);
    s = fmaf(f3.x, c[6], s);
    s = fmaf(f3.y, c[7], s);
    return s;
}

__device__ __forceinline__ void cvt_c8(const uint4& C, float* c)
{
    const __half2* chh = reinterpret_cast<const __half2*>(&C);
    float2 f0 = __half22float2(chh[0]);
    float2 f1 = __half22float2(chh[1]);
    float2 f2 = __half22float2(chh[2]);
    float2 f3 = __half22float2(chh[3]);
    c[0] = f0.x; c[1] = f0.y; c[2] = f1.x; c[3] = f1.y;
    c[4] = f2.x; c[5] = f2.y; c[6] = f3.x; c[7] = f3.y;
}

__global__ void __launch_bounds__(128, 10) distmult_kernel(
    const int* __restrict__ edge_index,  // [2, E] int32
    const int* __restrict__ edge_type,   // [E] int32
    float* __restrict__ out,
    int E)
{
    int tid = blockIdx.x * blockDim.x + threadIdx.x;
    int g = tid >> 2;               // 4-lane group; handles edges 4g..4g+3
    unsigned i = threadIdx.x & 3u;  // 16B chunk within a 64B fp16 row
    int e0 = g * 4;
    if (e0 >= E) return;

    const uint4* __restrict__ xh = reinterpret_cast<const uint4*>(g_xh);  // row = 4 uint4
    const uint4* __restrict__ rh = reinterpret_cast<const uint4*>(g_rh);

    if (e0 + 3 < E) {
        int4 L  = reinterpret_cast<const int4*>(edge_index)[g];
        int4 Rt = reinterpret_cast<const int4*>(edge_index + E)[g];
        int t0 = edge_type[e0];
        int t3 = edge_type[e0 + 3];

        // 8 independent coalesced 16B gathers; warp covers 8 rows/instruction
        uint4 a0 = xh[(unsigned)L.x * 4u + i];
        uint4 a1 = xh[(unsigned)L.y * 4u + i];
        uint4 a2 = xh[(unsigned)L.z * 4u + i];
        uint4 a3 = xh[(unsigned)L.w * 4u + i];
        uint4 b0 = xh[(unsigned)Rt.x * 4u + i];
        uint4 b1 = xh[(unsigned)Rt.y * 4u + i];
        uint4 b2 = xh[(unsigned)Rt.z * 4u + i];
        uint4 b3 = xh[(unsigned)Rt.w * 4u + i];
        // hoisted: shared-relation row load overlaps the gathers above
        uint4 C0 = rh[(unsigned)t0 * 4u + i];

        float s0, s1, s2, s3;
        if (t0 == t3) {
            // sorted types: one shared R row (~99.9% of groups)
            float c[8];
            cvt_c8(C0, c);
            s0 = edge_score8(a0, b0, c);
            s1 = edge_score8(a1, b1, c);
            s2 = edge_score8(a2, b2, c);
            s3 = edge_score8(a3, b3, c);
        } else {
            // relation boundary inside the group (rare)
            float c[8];
            uint4 C;
            cvt_c8(C0, c);                                              s0 = edge_score8(a0, b0, c);
            C = rh[(unsigned)edge_type[e0 + 1] * 4u + i]; cvt_c8(C, c); s1 = edge_score8(a1, b1, c);
            C = rh[(unsigned)edge_type[e0 + 2] * 4u + i]; cvt_c8(C, c); s2 = edge_score8(a2, b2, c);
            C = rh[(unsigned)t3 * 4u + i];                cvt_c8(C, c); s3 = edge_score8(a3, b3, c);
        }

        // packed 4-lane reduction of 4 values: 3 SHFLs
        bool b2sel = (i & 2u) != 0u;
        float kA = b2sel ? s1 : s0, sA = b2sel ? s0 : s1;
        kA += __shfl_xor_sync(0xFFFFFFFFu, sA, 2);
        float kB = b2sel ? s3 : s2, sB = b2sel ? s2 : s3;
        kB += __shfl_xor_sync(0xFFFFFFFFu, sB, 2);
        bool b1sel = (i & 1u) != 0u;
        float keep = b1sel ? kB : kA, send = b1sel ? kA : kB;
        keep += __shfl_xor_sync(0xFFFFFFFFu, send, 1);
        // lane i holds edge e0 + (((i&1)<<1) | (i>>1)): lanes {0,1,2,3} -> edges {0,2,1,3}

        int j = (int)(((i & 1u) << 1) | (i >> 1));
        out[e0 + j] = 1.0f / (1.0f + __expf(-keep));  // 32 consecutive floats per warp
    } else {
        // scalar tail (unused when E % 4 == 0, kept for safety)
        for (int e = e0; e < E; e++) {
            int l = edge_index[e];
            int r = edge_index[E + e];
            int t = edge_type[e];
            uint4 a = xh[(unsigned)l * 4u + i];
            uint4 b = xh[(unsigned)r * 4u + i];
            uint4 C = rh[(unsigned)t * 4u + i];
            float c[8];
            cvt_c8(C, c);
            float s = edge_score8(a, b, c);
            s += __shfl_xor_sync(0xFFFFFFFFu, s, 1);
            s += __shfl_xor_sync(0xFFFFFFFFu, s, 2);
            if (i == 0u) out[e] = 1.0f / (1.0f + __expf(-s));
        }
    }
}

extern "C" void kernel_launch(void* const* d_in, const int* in_sizes, int n_in,
                              void* d_out, int out_size)
{
    const float* x  = (const float*)d_in[0];   // [N_NODES, 32] fp32
    const float* R  = (const float*)d_in[1];   // [N_REL, 32] fp32
    const int*   ei = (const int*)d_in[2];     // [2, E] int32
    const int*   et = (const int*)d_in[3];     // [E] int32
    float* out = (float*)d_out;

    int E = in_sizes[3];
    int n2x = in_sizes[0] / 2;   // float pairs in x
    int n2r = in_sizes[1] / 2;   // float pairs in R

    // Kernel 1: fp32 -> fp16 tables for x and R
    {
        const int threads = 256;
        int total = n2x + n2r;
        int blocks = (total + threads - 1) / threads;
        convert_kernel<<<blocks, threads>>>(reinterpret_cast<const float2*>(x), n2x,
                                            reinterpret_cast<const float2*>(R), n2r);
    }

    // Kernel 2: gather + score
    {
        const int threads = 128;
        long long groups = ((long long)E + 3) / 4;   // 4 edges per 4-lane group
        long long total = groups * 4;
        int blocks = (int)((total + threads - 1) / threads);
        distmult_kernel<<<blocks, threads>>>(ei, et, out, E);
    }
}